// round 1
// baseline (speedup 1.0000x reference)
#include <cuda_runtime.h>
#include <math.h>

// Problem dims
#define BB 8
#define CI 64
#define CO 128
#define HH 256
#define WW 256

// Output offsets (ll, m_ll, lh, hl, hh, m_lh, m_hl, m_hh)
#define SUB (BB*CO*128*128)      // 16777216
#define MSK (BB*128*128)         // 131072
#define OFF_LL  0
#define OFF_MLL (SUB)
#define OFF_LH  (SUB + MSK)
#define OFF_HL  (2*SUB + MSK)
#define OFF_HH  (3*SUB + MSK)
#define OFF_MLH (4*SUB + MSK)
#define OFF_MHL (4*SUB + 2*MSK)
#define OFF_MHH (4*SUB + 3*MSK)

// Scratch
__device__ float g_x[(size_t)BB*CO*HH*WW];     // conv out, then GDN in-place
__device__ float g_ratio[BB*HH*WW];            // >0 <=> valid
__device__ float g_inv_sigma;

__constant__ float c_h0[9] = {
    0.026748757410810f, -0.016864118442875f, -0.078223266528990f,
    0.266864118442875f,  0.602949018236360f,  0.266864118442875f,
   -0.078223266528990f, -0.016864118442875f,  0.026748757410810f};
__constant__ float c_h1[7] = {
    0.091271763114250f, -0.057543526228500f, -0.591271763114250f,
    1.115087052457000f, -0.591271763114250f, -0.057543526228500f,
    0.091271763114250f};

__device__ __forceinline__ int refl(int i, int n) {
    return i < 0 ? -i : (i >= n ? 2*n - 2 - i : i);
}

// ---------------------------------------------------------------------------
// Spectral norm: one power-iteration step, writes 1/sigma
// ---------------------------------------------------------------------------
__global__ void spectral_kernel(const float* __restrict__ w,
                                const float* __restrict__ u)
{
    __shared__ float sv[576];
    __shared__ float red[256];
    int tid = threadIdx.x;
    float p = 0.f;
    for (int j = tid; j < 576; j += 256) {
        float s = 0.f;
        #pragma unroll 4
        for (int o = 0; o < 128; ++o) s += w[o*576 + j] * u[o];
        sv[j] = s;
        p += s * s;
    }
    red[tid] = p; __syncthreads();
    for (int s = 128; s > 0; s >>= 1) {
        if (tid < s) red[tid] += red[tid + s];
        __syncthreads();
    }
    float vinv = 1.f / (sqrtf(red[0]) + 1e-12f);
    __syncthreads();
    float q = 0.f;
    if (tid < 128) {
        float s = 0.f;
        #pragma unroll 4
        for (int j = 0; j < 576; ++j) s += w[tid*576 + j] * sv[j];
        s *= vinv;
        q = s * s;
    }
    red[tid] = q; __syncthreads();
    for (int s = 128; s > 0; s >>= 1) {
        if (tid < s) red[tid] += red[tid + s];
        __syncthreads();
    }
    if (tid == 0) g_inv_sigma = rsqrtf(red[0]);
}

// ---------------------------------------------------------------------------
// Partial-conv mask renormalization: ratio = valid ? 9/msum : 0
// ---------------------------------------------------------------------------
__global__ void ratio_kernel(const float* __restrict__ mask)
{
    int idx = blockIdx.x * 256 + threadIdx.x;
    if (idx >= BB*HH*WW) return;
    int b = idx >> 16, rem = idx & 65535;
    int h = rem >> 8, wq = rem & 255;
    float s = 0.f;
    #pragma unroll
    for (int dh = -1; dh <= 1; ++dh) {
        int gh = h + dh;
        if ((unsigned)gh >= (unsigned)HH) continue;
        #pragma unroll
        for (int dw = -1; dw <= 1; ++dw) {
            int gw = wq + dw;
            if ((unsigned)gw >= (unsigned)WW) continue;
            s += mask[(b*HH + gh)*WW + gw];
        }
    }
    g_ratio[idx] = s > 0.f ? 9.f / fmaxf(s, 1e-8f) : 0.f;
}

// ---------------------------------------------------------------------------
// Partial conv 3x3 (spectral-normalized), fused mask multiply + renorm + bias
// Block: 32 oc x (8h x 32w) tile, 256 threads, 8-channel smem chunks
// ---------------------------------------------------------------------------
__global__ __launch_bounds__(256, 2)
void conv_kernel(const float* __restrict__ x, const float* __restrict__ mask,
                 const float* __restrict__ weight, const float* __restrict__ bias)
{
    __shared__ float sIn[8][10][34];
    __shared__ float sW[8][32][9];
    __shared__ float sM[10][34];

    int tid  = threadIdx.x;
    int lane = tid & 31;
    int g    = tid >> 5;                 // oc sub-group 0..7
    int b    = blockIdx.z >> 2;
    int ocBlock = (blockIdx.z & 3) * 32;
    int h0 = blockIdx.y * 8, w0 = blockIdx.x * 32;
    float inv_sigma = g_inv_sigma;

    for (int i = tid; i < 340; i += 256) {
        int r = i / 34, cc = i % 34;
        int gh = h0 - 1 + r, gw = w0 - 1 + cc;
        float v = 0.f;
        if ((unsigned)gh < (unsigned)HH && (unsigned)gw < (unsigned)WW)
            v = mask[(b*HH + gh)*WW + gw];
        sM[r][cc] = v;
    }

    float acc[4][8];
    #pragma unroll
    for (int o = 0; o < 4; ++o)
        #pragma unroll
        for (int r = 0; r < 8; ++r) acc[o][r] = 0.f;

    for (int ch = 0; ch < CI; ch += 8) {
        __syncthreads();
        for (int i = tid; i < 2720; i += 256) {
            int c = i / 340, j = i % 340;
            int r = j / 34, cc = j % 34;
            int gh = h0 - 1 + r, gw = w0 - 1 + cc;
            float v = 0.f;
            if ((unsigned)gh < (unsigned)HH && (unsigned)gw < (unsigned)WW)
                v = x[(((size_t)b*CI + ch + c)*HH + gh)*WW + gw] * sM[r][cc];
            sIn[c][r][cc] = v;
        }
        for (int i = tid; i < 2304; i += 256) {
            int c = i / 288, rem = i % 288;
            int oc = rem / 9, k = rem % 9;
            sW[c][oc][k] = weight[((ocBlock + oc)*CI + ch + c)*9 + k] * inv_sigma;
        }
        __syncthreads();

        #pragma unroll
        for (int c = 0; c < 8; ++c) {
            float wr[4][9];
            #pragma unroll
            for (int o = 0; o < 4; ++o)
                #pragma unroll
                for (int k = 0; k < 9; ++k) wr[o][k] = sW[c][g*4 + o][k];

            float a0 = sIn[c][0][lane], a1 = sIn[c][0][lane+1], a2 = sIn[c][0][lane+2];
            float b0 = sIn[c][1][lane], b1 = sIn[c][1][lane+1], b2 = sIn[c][1][lane+2];
            #pragma unroll
            for (int r = 0; r < 8; ++r) {
                float d0 = sIn[c][r+2][lane], d1 = sIn[c][r+2][lane+1], d2 = sIn[c][r+2][lane+2];
                #pragma unroll
                for (int o = 0; o < 4; ++o) {
                    acc[o][r] += a0*wr[o][0] + a1*wr[o][1] + a2*wr[o][2]
                               + b0*wr[o][3] + b1*wr[o][4] + b2*wr[o][5]
                               + d0*wr[o][6] + d1*wr[o][7] + d2*wr[o][8];
                }
                a0 = b0; a1 = b1; a2 = b2;
                b0 = d0; b1 = d1; b2 = d2;
            }
        }
    }

    #pragma unroll
    for (int r = 0; r < 8; ++r) {
        int h = h0 + r, wq = w0 + lane;
        float ratio = g_ratio[(b*HH + h)*WW + wq];
        bool valid = ratio > 0.f;
        #pragma unroll
        for (int o = 0; o < 4; ++o) {
            int oc = ocBlock + g*4 + o;
            float v = valid ? acc[o][r]*ratio + bias[oc] : 0.f;
            g_x[(((size_t)b*CO + oc)*HH + h)*WW + wq] = v;
        }
    }
}

// ---------------------------------------------------------------------------
// Partial GDN: y = x / sqrt(beta + gamma @ x^2), in-place on g_x
// ---------------------------------------------------------------------------
#define GDN_GSTRIDE 132
#define GDN_SMEM ((128*GDN_GSTRIDE + 128*64) * 4)

__global__ __launch_bounds__(256, 2)
void gdn_kernel(const float* __restrict__ gamma, const float* __restrict__ beta)
{
    extern __shared__ float sm[];
    float* sG = sm;                       // [c][o], stride 132
    float* sX = sm + 128*GDN_GSTRIDE;     // [c][pix], 64 pix

    int tid = threadIdx.x;
    for (int i = tid; i < 128*128; i += 256) {
        int o = i >> 7, c = i & 127;
        sG[c*GDN_GSTRIDE + o] = gamma[i];
    }
    __syncthreads();

    int og = tid >> 4;          // 0..15 -> o0 = og*8
    int pg = tid & 15;          // 0..15 -> 4 pixels each
    int o0 = og * 8;
    float be[8];
    #pragma unroll
    for (int oi = 0; oi < 8; ++oi) be[oi] = __ldg(&beta[o0 + oi]);

    const float4* sGv = (const float4*)sG;   // row stride 33
    const float4* sXv = (const float4*)sX;   // row stride 16
    float4* sXw = (float4*)sX;

    const int nTiles = BB * HH * WW / 64;    // 8192
    for (int t = blockIdx.x; t < nTiles; t += gridDim.x) {
        int b = t >> 10;
        int base = (t & 1023) * 64;

        for (int i = tid; i < 128*16; i += 256) {
            int c = i >> 4, pv = i & 15;
            sXw[c*16 + pv] =
                ((const float4*)(g_x + ((size_t)(b*CO + c))*HH*WW + base))[pv];
        }
        __syncthreads();

        float acc[32];
        #pragma unroll
        for (int i = 0; i < 32; ++i) acc[i] = 0.f;

        #pragma unroll 2
        for (int c = 0; c < 128; ++c) {
            float4 xv = sXv[c*16 + pg];
            float xs[4] = {xv.x*xv.x, xv.y*xv.y, xv.z*xv.z, xv.w*xv.w};
            float4 ga = sGv[c*33 + (og << 1)];
            float4 gb = sGv[c*33 + (og << 1) + 1];
            float g8[8] = {ga.x, ga.y, ga.z, ga.w, gb.x, gb.y, gb.z, gb.w};
            #pragma unroll
            for (int oi = 0; oi < 8; ++oi)
                #pragma unroll
                for (int pi = 0; pi < 4; ++pi)
                    acc[oi*4 + pi] += g8[oi] * xs[pi];
        }

        #pragma unroll
        for (int oi = 0; oi < 8; ++oi) {
            float4 xv = sXv[(o0 + oi)*16 + pg];
            float4 yv;
            yv.x = xv.x * rsqrtf(be[oi] + acc[oi*4 + 0]);
            yv.y = xv.y * rsqrtf(be[oi] + acc[oi*4 + 1]);
            yv.z = xv.z * rsqrtf(be[oi] + acc[oi*4 + 2]);
            yv.w = xv.w * rsqrtf(be[oi] + acc[oi*4 + 3]);
            ((float4*)(g_x + ((size_t)(b*CO + o0 + oi))*HH*WW + base))[pg] = yv;
        }
        __syncthreads();
    }
}

// ---------------------------------------------------------------------------
// Fused 2D DWT (CDF 9/7 analysis), both separable stages in smem
// Block: one (b,c), 16x32 output tile per subband
// ---------------------------------------------------------------------------
__global__ __launch_bounds__(256)
void dwt_kernel(float* __restrict__ out)
{
    __shared__ float sT[40][72];
    __shared__ float sLo[16][72];
    __shared__ float sHi[16][72];

    int tid = threadIdx.x;
    int z = blockIdx.z;                       // b*128 + c
    int hb = blockIdx.y * 16, wb = blockIdx.x * 32;
    const float* src = g_x + (size_t)z * HH * WW;

    for (int i = tid; i < 40*72; i += 256) {
        int r = i / 72, cc = i % 72;
        int gr = refl(2*hb - 4 + r, HH);
        int gc = refl(2*wb - 4 + cc, WW);
        sT[r][cc] = src[gr*WW + gc];
    }
    __syncthreads();

    for (int i = tid; i < 16*72; i += 256) {
        int r = i / 72, cc = i % 72;
        float lo = 0.f, hi = 0.f;
        #pragma unroll
        for (int k = 0; k < 9; ++k) lo += c_h0[k] * sT[2*r + k][cc];
        #pragma unroll
        for (int k = 0; k < 7; ++k) hi += c_h1[k] * sT[2*r + k + 1][cc];
        sLo[r][cc] = lo;
        sHi[r][cc] = hi;
    }
    __syncthreads();

    for (int i = tid; i < 16*32; i += 256) {
        int r = i / 32, co = i % 32;
        float ll = 0.f, lh = 0.f, hl = 0.f, hh = 0.f;
        #pragma unroll
        for (int k = 0; k < 9; ++k) {
            ll += c_h0[k] * sLo[r][2*co + k];
            hl += c_h0[k] * sHi[r][2*co + k];
        }
        #pragma unroll
        for (int k = 0; k < 7; ++k) {
            lh += c_h1[k] * sLo[r][2*co + k + 1];
            hh += c_h1[k] * sHi[r][2*co + k + 1];
        }
        size_t idx = (size_t)z*16384 + (size_t)(hb + r)*128 + (wb + co);
        out[OFF_LL + idx] = ll;
        out[OFF_LH + idx] = lh;
        out[OFF_HL + idx] = hl;
        out[OFF_HH + idx] = hh;
    }
}

// ---------------------------------------------------------------------------
// Mask DWT: count>0 composition == OR over reflected 9/7 windows
// ---------------------------------------------------------------------------
__global__ void maskdwt_kernel(float* __restrict__ out)
{
    int idx = blockIdx.x * 256 + threadIdx.x;
    if (idx >= BB*128*128) return;
    int b = idx >> 14, rem = idx & 16383;
    int ho = rem >> 7, wo = rem & 127;

    bool mll = false, mlh = false, mhl = false, mhh = false;
    #pragma unroll
    for (int dr = -4; dr <= 4; ++dr) {
        int gr = refl(2*ho + dr, HH);
        bool row9 = false, row7 = false;
        #pragma unroll
        for (int dc = -4; dc <= 4; ++dc) {
            int gc = refl(2*wo + dc, WW);
            bool v = g_ratio[(b*HH + gr)*WW + gc] > 0.f;
            row9 |= v;
            if (dc >= -3 && dc <= 3) row7 |= v;
        }
        mll |= row9;
        mlh |= row7;
        if (dr >= -3 && dr <= 3) { mhl |= row9; mhh |= row7; }
    }
    out[OFF_MLL + idx] = mll ? 1.f : 0.f;
    out[OFF_MLH + idx] = mlh ? 1.f : 0.f;
    out[OFF_MHL + idx] = mhl ? 1.f : 0.f;
    out[OFF_MHH + idx] = mhh ? 1.f : 0.f;
}

// ---------------------------------------------------------------------------
extern "C" void kernel_launch(void* const* d_in, const int* in_sizes, int n_in,
                              void* d_out, int out_size)
{
    const float* tensor = (const float*)d_in[0];
    const float* mask   = (const float*)d_in[1];
    const float* weight = (const float*)d_in[2];
    const float* bias   = (const float*)d_in[3];
    const float* u      = (const float*)d_in[4];
    const float* beta   = (const float*)d_in[5];
    const float* gamma  = (const float*)d_in[6];
    float* out = (float*)d_out;

    cudaFuncSetAttribute(gdn_kernel,
                         cudaFuncAttributeMaxDynamicSharedMemorySize, GDN_SMEM);

    spectral_kernel<<<1, 256>>>(weight, u);
    ratio_kernel<<<(BB*HH*WW + 255)/256, 256>>>(mask);
    conv_kernel<<<dim3(WW/32, HH/8, BB*4), 256>>>(tensor, mask, weight, bias);
    gdn_kernel<<<296, 256, GDN_SMEM>>>(gamma, beta);
    dwt_kernel<<<dim3(4, 8, BB*CO), 256>>>(out);
    maskdwt_kernel<<<(BB*128*128 + 255)/256, 256>>>(out);
}